// round 2
// baseline (speedup 1.0000x reference)
#include <cuda_runtime.h>
#include <math.h>

#define BN   16
#define KCH  10
#define H    224
#define W    224
#define PADR 7
#define TS   15
#define TT   225          // TS*TS
#define HPAD 238
#define WPAD 238
#define NPIX (BN*H*W)     // 802816
#define NCTA 296
#define YSTAGE 32
#define PELEM (TT*KCH*KCH)  // 22500

// ---------------- scratch (static device allocations) ----------------
__device__ float g_Xpad[(size_t)BN*HPAD*WPAD*KCH];   // padded NHWC x_out  (~36 MB)
__device__ float g_Yn[(size_t)NPIX*KCH];             // NHWC x_tf_out      (~32 MB)
__device__ float g_part[(size_t)NCTA*PELEM];         // per-CTA partial hist (~27 MB)
__device__ float g_p[PELEM];                         // reduced joint hist
__device__ float g_min[1];

typedef unsigned long long ull;

__device__ __forceinline__ ull pack2(float lo, float hi) {
    ull r; asm("mov.b64 %0,{%1,%2};" : "=l"(r) : "f"(lo), "f"(hi)); return r;
}
__device__ __forceinline__ void unpack2(ull v, float& lo, float& hi) {
    asm("mov.b64 {%0,%1},%2;" : "=f"(lo), "=f"(hi) : "l"(v));
}
__device__ __forceinline__ ull fma2(ull a, ull b, ull c) {
    ull d; asm("fma.rn.f32x2 %0,%1,%2,%3;" : "=l"(d) : "l"(a), "l"(b), "l"(c)); return d;
}

// ------------- pack x_out (b,k,h,w) -> zero-padded NHWC (b,yy,xx,k) -------------
__global__ void pack_x_kernel(const float* __restrict__ x) {
    int idx = blockIdx.x * blockDim.x + threadIdx.x;
    if (idx >= BN*HPAD*WPAD) return;
    int b  = idx / (HPAD*WPAD);
    int r  = idx % (HPAD*WPAD);
    int yy = r / WPAD, xx = r % WPAD;
    int sy = yy - PADR, sx = xx - PADR;
    bool inb = (sy >= 0) && (sy < H) && (sx >= 0) && (sx < W);
    float v[KCH];
#pragma unroll
    for (int n = 0; n < KCH; n++)
        v[n] = inb ? x[(((size_t)b*KCH + n)*H + sy)*W + sx] : 0.0f;
    float2* dst = reinterpret_cast<float2*>(&g_Xpad[(size_t)idx*KCH]);
#pragma unroll
    for (int i = 0; i < 5; i++) dst[i] = make_float2(v[2*i], v[2*i+1]);
}

// ------------- pack x_tf_out (b,k,h,w) -> NHWC (b,y,x,k) -------------
__global__ void pack_y_kernel(const float* __restrict__ y) {
    int idx = blockIdx.x * blockDim.x + threadIdx.x;
    if (idx >= NPIX) return;
    int b  = idx / (H*W);
    int r  = idx % (H*W);
    int yy = r / W, xx = r % W;
    float v[KCH];
#pragma unroll
    for (int n = 0; n < KCH; n++)
        v[n] = y[(((size_t)b*KCH + n)*H + yy)*W + xx];
    float2* dst = reinterpret_cast<float2*>(&g_Yn[(size_t)idx*KCH]);
#pragma unroll
    for (int i = 0; i < 5; i++) dst[i] = make_float2(v[2*i], v[2*i+1]);
}

// ------------- main correlation: thread = (shift, o-half), 25 f32x2 accumulators -------------
__global__ __launch_bounds__(480, 1) void corr_kernel() {
    __shared__ float sY[YSTAGE*KCH];

    int t = threadIdx.x;
    bool active = (t < 450);
    int s  = t >> 1; if (s > TT-1) s = TT-1;
    int oh = t & 1;
    int dy = s / TS, dx = s % TS;

    const int chunk = (NPIX + NCTA - 1) / NCTA;
    int p0 = blockIdx.x * chunk;
    int p1 = min(p0 + chunk, NPIX);

    int b0 = p0 / (H*W);
    int r0 = p0 % (H*W);
    int y0 = r0 / W;
    int x0 = r0 % W;
    int xcur = x0, ycur = y0;
    int base = ((b0*HPAD + y0 + dy)*WPAD + (x0 + dx))*KCH;

    ull acc[5][5];
#pragma unroll
    for (int i = 0; i < 5; i++)
#pragma unroll
        for (int j = 0; j < 5; j++) acc[i][j] = 0ull;   // bits of (0.0f, 0.0f)

    int sidx = YSTAGE;  // force stage on first iteration
    for (int p = p0; p < p1; ++p) {
        if (sidx == YSTAGE) {
            __syncthreads();
            if (t < YSTAGE*KCH) {
                // thread t stages element t of the 32-pixel Y window starting at p
                int pix = p + t / KCH;
                sY[t] = (pix < NPIX) ? g_Yn[(size_t)p*KCH + t] : 0.0f;
            }
            __syncthreads();
            sidx = 0;
        }
        if (active) {
            const ull* xp = reinterpret_cast<const ull*>(&g_Xpad[(size_t)base]);
            ull xv[5];
#pragma unroll
            for (int i = 0; i < 5; i++) xv[i] = __ldg(xp + i);
            const float* yr = &sY[sidx*KCH + oh*5];
            ull yd[5];
#pragma unroll
            for (int j = 0; j < 5; j++) { float yv = yr[j]; yd[j] = pack2(yv, yv); }
#pragma unroll
            for (int j = 0; j < 5; j++) {
#pragma unroll
                for (int i = 0; i < 5; i++)
                    acc[i][j] = fma2(xv[i], yd[j], acc[i][j]);
            }
        }
        sidx++;
        base += KCH;                       // x -> x+1
        xcur++;
        if (xcur == W) {                   // row wrap: +(WPAD-W)*KCH extra
            xcur = 0; ycur++;
            base += (WPAD - W)*KCH;        // 140
            if (ycur == H) {               // batch wrap: +(HPAD-H)*WPAD*KCH extra
                ycur = 0;
                base += (HPAD - H)*WPAD*KCH;  // 33320
            }
        }
    }

    if (active) {
        float* dst = g_part + (size_t)blockIdx.x*PELEM + (size_t)s*KCH*KCH;
#pragma unroll
        for (int i = 0; i < 5; i++) {
#pragma unroll
            for (int j = 0; j < 5; j++) {
                float lo, hi;
                unpack2(acc[i][j], lo, hi);
                dst[(2*i  )*KCH + oh*5 + j] = lo;   // n = 2i
                dst[(2*i+1)*KCH + oh*5 + j] = hi;   // n = 2i+1
            }
        }
    }
}

// ------------- reduce partials over CTAs -------------
__global__ void reduce_kernel() {
    int e = blockIdx.x * blockDim.x + threadIdx.x;
    if (e >= PELEM) return;
    float sum = 0.0f;
    for (int c = 0; c < NCTA; c++)
        sum += g_part[(size_t)c*PELEM + e];
    g_p[e] = sum;
}

// ------------- global min over joint histogram -------------
__global__ void min_kernel() {
    __shared__ float sm[1024];
    int t = threadIdx.x;
    float m = 3.4e38f;
    for (int e = t; e < PELEM; e += 1024) m = fminf(m, g_p[e]);
    sm[t] = m;
    __syncthreads();
    for (int w2 = 512; w2 > 0; w2 >>= 1) {
        if (t < w2) sm[t] = fminf(sm[t], sm[t + w2]);
        __syncthreads();
    }
    if (t == 0) g_min[0] = sm[0];
}

// ------------- loss epilogue (exact reference math, fp32) -------------
__global__ void loss_kernel(float* __restrict__ out) {
    __shared__ float ssum[256];
    int t = threadIdx.x;
    float part = 0.0f;
    const float EPS = 1e-16f;
    if (t < TT) {
        const float m = g_min[0];
        float v[KCH*KCH];          // per-shift 10x10 joint, register-resident
        float tot = 0.0f;
        for (int e = 0; e < KCH*KCH; e++) {
            float q = g_p[t*KCH*KCH + e] - m + EPS;
            v[e] = q;
            tot += q;
        }
        float inv = 1.0f / tot;
        float pi[KCH], pj[KCH];
#pragma unroll
        for (int o = 0; o < KCH; o++) { pi[o] = 0.0f; pj[o] = 0.0f; }
        for (int n = 0; n < KCH; n++)
            for (int o = 0; o < KCH; o++) {
                float q = 0.5f * (v[n*KCH + o] + v[o*KCH + n]) * inv;
                pi[o] += q;   // sum over n (axis=2)
                pj[n] += q;   // sum over o (axis=3)
            }
        for (int n = 0; n < KCH; n++)
            for (int o = 0; o < KCH; o++) {
                float q = 0.5f * (v[n*KCH + o] + v[o*KCH + n]) * inv;
                part += -q * (logf(q + EPS) - logf(pi[o] + EPS) - logf(pj[n] + EPS));
            }
    }
    ssum[t] = part;
    __syncthreads();
    for (int w2 = 128; w2 > 0; w2 >>= 1) {
        if (t < w2) ssum[t] += ssum[t + w2];
        __syncthreads();
    }
    if (t == 0) out[0] = ssum[0] / (float)TT;
}

// ------------- launch -------------
extern "C" void kernel_launch(void* const* d_in, const int* in_sizes, int n_in,
                              void* d_out, int out_size) {
    const float* x = (const float*)d_in[0];   // x_out     (16,10,224,224) f32
    const float* y = (const float*)d_in[1];   // x_tf_out  (16,10,224,224) f32
    float* out = (float*)d_out;

    pack_x_kernel<<<(BN*HPAD*WPAD + 255)/256, 256>>>(x);
    pack_y_kernel<<<(NPIX + 255)/256, 256>>>(y);
    corr_kernel<<<NCTA, 480>>>();
    reduce_kernel<<<(PELEM + 255)/256, 256>>>();
    min_kernel<<<1, 1024>>>();
    loss_kernel<<<1, 256>>>(out);
}

// round 3
// speedup vs baseline: 1.8757x; 1.8757x over previous
#include <cuda_runtime.h>
#include <math.h>

#define BN   16
#define KCH  10
#define H    224
#define W    224
#define PADR 7
#define TS   15
#define TT   225
#define HPAD 238
#define WPAD 238
#define NPIX (BN*H*W)       // 802816
#define GRID 148
#define TY   4                       // rows per tile strip
#define NTILES (BN*(H/TY))           // 896
#define PELEM (TT*KCH*KCH)           // 22500

#define SX_FLOATS ((TY+2*PADR)*WPAD*KCH)   // 18*238*10 = 42840
#define SY_FLOATS (TY*W*KCH)               // 4*224*10  = 8960
#define SMEM_BYTES ((SX_FLOATS + SY_FLOATS)*4)   // 207200

// ---------------- scratch (static device allocations) ----------------
__device__ float g_Xpad[(size_t)BN*HPAD*WPAD*KCH];   // padded NHWC x_out  (~36 MB)
__device__ float g_Yn[(size_t)NPIX*KCH];             // NHWC x_tf_out      (~32 MB)
__device__ float g_part[(size_t)GRID*PELEM];         // per-CTA partials   (~13 MB)
__device__ float g_p[PELEM];
__device__ float g_min[1];

typedef unsigned long long ull;

__device__ __forceinline__ ull pack2(float lo, float hi) {
    ull r; asm("mov.b64 %0,{%1,%2};" : "=l"(r) : "f"(lo), "f"(hi)); return r;
}
__device__ __forceinline__ void unpack2(ull v, float& lo, float& hi) {
    asm("mov.b64 {%0,%1},%2;" : "=f"(lo), "=f"(hi) : "l"(v));
}
__device__ __forceinline__ ull fma2(ull a, ull b, ull c) {
    ull d; asm("fma.rn.f32x2 %0,%1,%2,%3;" : "=l"(d) : "l"(a), "l"(b), "l"(c)); return d;
}

// ------------- pack x_out (b,k,h,w) -> zero-padded NHWC (b,yy,xx,k) -------------
__global__ void pack_x_kernel(const float* __restrict__ x) {
    int idx = blockIdx.x * blockDim.x + threadIdx.x;
    if (idx >= BN*HPAD*WPAD) return;
    int b  = idx / (HPAD*WPAD);
    int r  = idx % (HPAD*WPAD);
    int yy = r / WPAD, xx = r % WPAD;
    int sy = yy - PADR, sx = xx - PADR;
    bool inb = (sy >= 0) && (sy < H) && (sx >= 0) && (sx < W);
    float v[KCH];
#pragma unroll
    for (int n = 0; n < KCH; n++)
        v[n] = inb ? x[(((size_t)b*KCH + n)*H + sy)*W + sx] : 0.0f;
    float2* dst = reinterpret_cast<float2*>(&g_Xpad[(size_t)idx*KCH]);
#pragma unroll
    for (int i = 0; i < 5; i++) dst[i] = make_float2(v[2*i], v[2*i+1]);
}

// ------------- pack x_tf_out (b,k,h,w) -> NHWC (b,y,x,k) -------------
__global__ void pack_y_kernel(const float* __restrict__ y) {
    int idx = blockIdx.x * blockDim.x + threadIdx.x;
    if (idx >= NPIX) return;
    int b  = idx / (H*W);
    int r  = idx % (H*W);
    int yy = r / W, xx = r % W;
    float v[KCH];
#pragma unroll
    for (int n = 0; n < KCH; n++)
        v[n] = y[(((size_t)b*KCH + n)*H + yy)*W + xx];
    float2* dst = reinterpret_cast<float2*>(&g_Yn[(size_t)idx*KCH]);
#pragma unroll
    for (int i = 0; i < 5; i++) dst[i] = make_float2(v[2*i], v[2*i+1]);
}

// ------------- main correlation: SMEM-tiled, thread = (shift, o-half) -------------
__global__ __launch_bounds__(480, 1) void corr_kernel() {
    extern __shared__ float smem[];
    float* sX = smem;                 // (TY+14) x 238 x 10
    float* sY = smem + SX_FLOATS;     // TY x 224 x 10

    int t = threadIdx.x;
    bool active = (t < 450);
    int s  = t >> 1; if (s > TT-1) s = TT-1;
    int oh = t & 1;
    int dy = s / TS, dx = s % TS;
    const int xbase0 = (dy*WPAD + dx)*KCH;

    ull acc[5][5];
#pragma unroll
    for (int i = 0; i < 5; i++)
#pragma unroll
        for (int j = 0; j < 5; j++) acc[i][j] = 0ull;

    for (int tau = blockIdx.x; tau < NTILES; tau += GRID) {
        int b  = tau / (H/TY);
        int y0 = (tau % (H/TY)) * TY;

        __syncthreads();   // previous tile's compute done before overwrite
        {
            const float4* gx = reinterpret_cast<const float4*>(
                &g_Xpad[((size_t)(b*HPAD + y0))*WPAD*KCH]);
            float4* s4 = reinterpret_cast<float4*>(sX);
            for (int i = t; i < SX_FLOATS/4; i += 480) s4[i] = gx[i];
            const float4* gy = reinterpret_cast<const float4*>(
                &g_Yn[((size_t)(b*H + y0))*W*KCH]);
            float4* s4y = reinterpret_cast<float4*>(sY);
            for (int i = t; i < SY_FLOATS/4; i += 480) s4y[i] = gy[i];
        }
        __syncthreads();

        if (active) {
#pragma unroll
            for (int y = 0; y < TY; y++) {
                int xoff = xbase0 + y*WPAD*KCH;
                int yoff = y*W*KCH + oh*5;
#pragma unroll 2
                for (int x = 0; x < W; x++) {
                    const ull* xp = reinterpret_cast<const ull*>(&sX[xoff]);
                    ull xv[5];
#pragma unroll
                    for (int i = 0; i < 5; i++) xv[i] = xp[i];
                    ull yd[5];
#pragma unroll
                    for (int j = 0; j < 5; j++) { float yv = sY[yoff + j]; yd[j] = pack2(yv, yv); }
#pragma unroll
                    for (int j = 0; j < 5; j++) {
#pragma unroll
                        for (int i = 0; i < 5; i++)
                            acc[i][j] = fma2(xv[i], yd[j], acc[i][j]);
                    }
                    xoff += KCH; yoff += KCH;
                }
            }
        }
    }

    if (active) {
        float* dst = g_part + (size_t)blockIdx.x*PELEM + (size_t)s*KCH*KCH;
#pragma unroll
        for (int i = 0; i < 5; i++) {
#pragma unroll
            for (int j = 0; j < 5; j++) {
                float lo, hi;
                unpack2(acc[i][j], lo, hi);
                dst[(2*i  )*KCH + oh*5 + j] = lo;   // n = 2i
                dst[(2*i+1)*KCH + oh*5 + j] = hi;   // n = 2i+1
            }
        }
    }
}

// ------------- reduce partials over CTAs (float4-wide) -------------
__global__ void reduce_kernel() {
    int e = blockIdx.x * blockDim.x + threadIdx.x;   // float4 index
    if (e >= PELEM/4 + 1) return;
    if (4*e >= PELEM) return;
    // PELEM = 22500 = 4*5625 exactly
    float4 sum = make_float4(0.f, 0.f, 0.f, 0.f);
    const float4* src = reinterpret_cast<const float4*>(g_part);
    for (int c = 0; c < GRID; c++) {
        float4 v = src[(size_t)c*(PELEM/4) + e];
        sum.x += v.x; sum.y += v.y; sum.z += v.z; sum.w += v.w;
    }
    reinterpret_cast<float4*>(g_p)[e] = sum;
}

// ------------- global min over joint histogram -------------
__global__ void min_kernel() {
    __shared__ float sm[1024];
    int t = threadIdx.x;
    float m = 3.4e38f;
    for (int e = t; e < PELEM; e += 1024) m = fminf(m, g_p[e]);
    sm[t] = m;
    __syncthreads();
    for (int w2 = 512; w2 > 0; w2 >>= 1) {
        if (t < w2) sm[t] = fminf(sm[t], sm[t + w2]);
        __syncthreads();
    }
    if (t == 0) g_min[0] = sm[0];
}

// ------------- loss epilogue (exact reference math, fp32) -------------
__global__ void loss_kernel(float* __restrict__ out) {
    __shared__ float ssum[256];
    int t = threadIdx.x;
    float part = 0.0f;
    const float EPS = 1e-16f;
    if (t < TT) {
        const float m = g_min[0];
        float v[KCH*KCH];
        float tot = 0.0f;
        for (int e = 0; e < KCH*KCH; e++) {
            float q = g_p[t*KCH*KCH + e] - m + EPS;
            v[e] = q;
            tot += q;
        }
        float inv = 1.0f / tot;
        float pi[KCH], pj[KCH];
#pragma unroll
        for (int o = 0; o < KCH; o++) { pi[o] = 0.0f; pj[o] = 0.0f; }
        for (int n = 0; n < KCH; n++)
            for (int o = 0; o < KCH; o++) {
                float q = 0.5f * (v[n*KCH + o] + v[o*KCH + n]) * inv;
                pi[o] += q;
                pj[n] += q;
            }
        for (int n = 0; n < KCH; n++)
            for (int o = 0; o < KCH; o++) {
                float q = 0.5f * (v[n*KCH + o] + v[o*KCH + n]) * inv;
                part += -q * (logf(q + EPS) - logf(pi[o] + EPS) - logf(pj[n] + EPS));
            }
    }
    ssum[t] = part;
    __syncthreads();
    for (int w2 = 128; w2 > 0; w2 >>= 1) {
        if (t < w2) ssum[t] += ssum[t + w2];
        __syncthreads();
    }
    if (t == 0) out[0] = ssum[0] / (float)TT;
}

// ------------- launch -------------
extern "C" void kernel_launch(void* const* d_in, const int* in_sizes, int n_in,
                              void* d_out, int out_size) {
    const float* x = (const float*)d_in[0];   // x_out     (16,10,224,224) f32
    const float* y = (const float*)d_in[1];   // x_tf_out  (16,10,224,224) f32
    float* out = (float*)d_out;

    cudaFuncSetAttribute(corr_kernel,
                         cudaFuncAttributeMaxDynamicSharedMemorySize, SMEM_BYTES);

    pack_x_kernel<<<(BN*HPAD*WPAD + 255)/256, 256>>>(x);
    pack_y_kernel<<<(NPIX + 255)/256, 256>>>(y);
    corr_kernel<<<GRID, 480, SMEM_BYTES>>>();
    reduce_kernel<<<(PELEM/4 + 255)/256, 256>>>();
    min_kernel<<<1, 1024>>>();
    loss_kernel<<<1, 256>>>(out);
}

// round 9
// speedup vs baseline: 6.4363x; 3.4314x over previous
#include <cuda_runtime.h>
#include <cuda_fp16.h>
#include <cstdint>
#include <math.h>

#define BN    16
#define KCH   10
#define H     224
#define W     224
#define TS    15
#define TT    225

#define CROW  240                  // canvas row stride (elements)
#define S_IMG (238*CROW)           // 57120 per image
#define KU    (BN*S_IMG)           // 913920
#define PS_X  922368               // X canvas plane size (covers u0max+6207+14*240)
#define PSY   918848               // Y canvas plane size (covers q up to 918,802)

#define TILEK 64
#define NTILE 97
#define CTAK  (NTILE*TILEK)        // 6208
#define GRIDG 148                  // 148*6208 = 918784 >= KU

#define SROW  144                  // smem row stride bytes (64 halves -> 128B, +16 pad)
#define MAT_BYTES (160*SROW)       // 23040
#define DSMEM (4*MAT_BYTES)        // A0 B0 A1 B1 = 92160

#define CN     160
#define PELEM2 (150*CN)            // 24000 per CTA
#define E4     (PELEM2/4)          // 6000

// ---------------- scratch ----------------
__device__ __align__(256) __half g_Xc[(size_t)KCH*PS_X];        // 18.4 MB
__device__ __align__(256) __half g_Yc[(size_t)4*KCH*PSY];       // 73.5 MB (4 parity canvases)
__device__ float g_part[(size_t)GRIDG*PELEM2];                  // 14.2 MB
__device__ float g_mid[(size_t)8*PELEM2];
__device__ float g_p[PELEM2];
__device__ float g_min[1];

// ---------------- PTX helpers (plain sm_80-era features only) ----------------
__device__ __forceinline__ uint32_t smem_u32(const void* p) {
    uint32_t a;
    asm("{ .reg .u64 t; cvta.to.shared.u64 t, %1; cvt.u32.u64 %0, t; }" : "=r"(a) : "l"(p));
    return a;
}
#define CP_COMMIT() asm volatile("cp.async.commit_group;" ::: "memory")
#define CP_WAIT1()  asm volatile("cp.async.wait_group 1;" ::: "memory")
#define CP_WAIT0()  asm volatile("cp.async.wait_group 0;" ::: "memory")

__device__ __forceinline__ void ldsm4(uint32_t& r0, uint32_t& r1, uint32_t& r2, uint32_t& r3,
                                      uint32_t addr) {
    asm volatile("ldmatrix.sync.aligned.m8n8.x4.shared.b16 {%0,%1,%2,%3}, [%4];"
                 : "=r"(r0), "=r"(r1), "=r"(r2), "=r"(r3) : "r"(addr));
}
__device__ __forceinline__ void mma16816(float* d,
        uint32_t a0, uint32_t a1, uint32_t a2, uint32_t a3,
        uint32_t b0, uint32_t b1) {
    asm volatile("mma.sync.aligned.m16n8k16.row.col.f32.f16.f16.f32 "
                 "{%0,%1,%2,%3}, {%4,%5,%6,%7}, {%8,%9}, {%0,%1,%2,%3};"
                 : "+f"(d[0]), "+f"(d[1]), "+f"(d[2]), "+f"(d[3])
                 : "r"(a0), "r"(a1), "r"(a2), "r"(a3), "r"(b0), "r"(b1));
}

// ---------------- pack x_out -> zero-padded fp16 canvas (Apad on 240-stride rows) ----------------
__global__ void pack_x_f16(const float* __restrict__ x) {
    int p = blockIdx.x * blockDim.x + threadIdx.x;
    int n = blockIdx.y;
    if (p >= PS_X) return;
    float v = 0.0f;
    if (p < KU) {
        int b  = p / S_IMG;
        int pp = p - b * S_IMG;
        int yy = pp / CROW, xx = pp - yy * CROW;
        if (yy >= 7 && yy < 231 && xx >= 7 && xx < 231)
            v = x[(((size_t)b*KCH + n)*H + (yy-7))*W + (xx-7)];
    }
    g_Xc[(size_t)n*PS_X + p] = __float2half(v);
}

// ---------------- pack x_tf_out -> 4 parity-shifted fp16 canvases ----------------
// Canvas s: C_s[q] = Y[q - 16 - s] (zero out of range). q entries [0,16) remain
// module-load zero (never written) == Y at negative index == 0. Deterministic.
__global__ void pack_y_f16(const float* __restrict__ y) {
    int p = blockIdx.x * blockDim.x + threadIdx.x;   // logical canvas index
    int o = blockIdx.y;
    if (p >= PSY) return;
    float v = 0.0f;
    if (p < KU) {
        int b  = p / S_IMG;
        int pp = p - b * S_IMG;
        int yy = pp / CROW, xx = pp - yy * CROW;
        if (yy < H && xx < W)
            v = y[(((size_t)b*KCH + o)*H + yy)*W + xx];
    }
    __half hv = __float2half(v);
#pragma unroll
    for (int s = 0; s < 4; s++) {
        int q = p + 16 + s;
        if (q < PSY) g_Yc[(size_t)(s*KCH + o)*PSY + q] = hv;
    }
}

// ---------------- staging: gather A'/B' K=64 tiles into SMEM via cp.async ----------------
// A' row r=(dy,n): Xc[n, u0 + c + dy*240], 150 rows x 64 halves (rows 150-159 stay zero)
// B' row r=(dx,o): Y[u0 + c - dx] via parity canvas s=dx&3 at q = u0 + c - dx + s + 16 (8B aligned)
__device__ __forceinline__ void stage(int u0, uint32_t sA, uint32_t sB, int tid) {
    for (int i = tid; i < 1200; i += 320) {            // 150 rows x 8 x 16B
        int r = i >> 3, c = i & 7;
        int dy = r / 10, n = r - dy*10;
        const __half* src = g_Xc + (size_t)n*PS_X + (u0 + dy*CROW + c*8);
        asm volatile("cp.async.ca.shared.global [%0], [%1], 16;"
                     :: "r"(sA + r*SROW + c*16), "l"(src));
    }
    for (int i = tid; i < 2400; i += 320) {            // 150 rows x 16 x 8B
        int r = i >> 4, c = i & 15;
        int dx = r / 10, o = r - dx*10;
        int s = dx & 3;
        int q = u0 + c*4 - dx + s + 16;                // == 0 mod 4 -> 8B aligned
        const __half* src = g_Yc + (size_t)(s*KCH + o)*PSY + q;
        asm volatile("cp.async.ca.shared.global [%0], [%1], 8;"
                     :: "r"(sB + r*SROW + c*8), "l"(src));
    }
}

// ---------------- per-tile warp MMA: strip m16 x N160, K=64 ----------------
__device__ __forceinline__ void compute_tile(uint32_t bufA, uint32_t bufB,
                                             int w, int l, float acc[20][4]) {
    uint32_t aBase = bufA + (16*w + (l & 15))*SROW + ((l >> 4) & 1)*16;
    uint32_t bOff  = ((l & 7) + ((l & 16) ? 8 : 0))*SROW + ((l & 8) ? 16 : 0);
#pragma unroll
    for (int kk = 0; kk < 4; kk++) {
        uint32_t a0, a1, a2, a3;
        ldsm4(a0, a1, a2, a3, aBase + kk*32);
#pragma unroll
        for (int t = 0; t < 10; t++) {
            uint32_t b0, b1, b2, b3;
            ldsm4(b0, b1, b2, b3, bufB + bOff + t*(16*SROW) + kk*32);
            mma16816(acc[2*t],     a0, a1, a2, a3, b0, b1);
            mma16816(acc[2*t + 1], a0, a1, a2, a3, b2, b3);
        }
    }
}

// ---------------- GEMM: C[150,150] += A'·B'^T over this CTA's K chunk ----------------
__global__ __launch_bounds__(320, 1) void gemm_kernel() {
    extern __shared__ char smem[];
    uint32_t sb = smem_u32(smem);
    int tid = threadIdx.x;
    int w = tid >> 5, l = tid & 31;

    // zero pad rows 150-159 of all 4 matrices (never touched by staging)
    for (int i = tid; i < 1440; i += 320) {
        int mtx = i / 360, off = i - mtx*360;
        *reinterpret_cast<uint32_t*>(smem + mtx*MAT_BYTES + 150*SROW + off*4) = 0;
    }

    int u0 = blockIdx.x * CTAK;

    stage(u0, sb, sb + MAT_BYTES, tid);
    CP_COMMIT();

    float acc[20][4];
#pragma unroll
    for (int j = 0; j < 20; j++)
#pragma unroll
        for (int c = 0; c < 4; c++) acc[j][c] = 0.0f;

    __syncthreads();   // pad zeros visible

    for (int i = 0; i < NTILE; i++) {
        if (i + 1 < NTILE) {
            uint32_t nb = sb + ((i + 1) & 1)*(2*MAT_BYTES);
            stage(u0 + (i + 1)*TILEK, nb, nb + MAT_BYTES, tid);
            CP_COMMIT();
            CP_WAIT1();           // tile i complete, tile i+1 in flight
        } else {
            CP_WAIT0();
        }
        __syncthreads();
        uint32_t cb = sb + (i & 1)*(2*MAT_BYTES);
        compute_tile(cb, cb + MAT_BYTES, w, l, acc);
        __syncthreads();          // done reading buf before it is restaged
    }

    // epilogue: fragment rows m0, m0+8; cols t*16 + {lo8, hi8}
    float* dst = g_part + (size_t)blockIdx.x * PELEM2;
    int m0 = 16*w + (l >> 2);
    int c0 = 2*(l & 3);
#pragma unroll
    for (int j = 0; j < 20; j++) {
        int n = j*8 + c0;
        if (m0 < 150) {
            dst[m0*CN + n]     = acc[j][0];
            dst[m0*CN + n + 1] = acc[j][1];
        }
        if (m0 + 8 < 150) {
            dst[(m0 + 8)*CN + n]     = acc[j][2];
            dst[(m0 + 8)*CN + n + 1] = acc[j][3];
        }
    }
}

// ---------------- reduce partials (2-stage for occupancy) ----------------
__global__ void reduce1_kernel() {
    int e = blockIdx.x * blockDim.x + threadIdx.x;   // float4 index
    if (e >= E4) return;
    int c0 = blockIdx.y * 19;
    int c1 = min(c0 + 19, GRIDG);
    float4 sum = make_float4(0.f, 0.f, 0.f, 0.f);
    const float4* src = reinterpret_cast<const float4*>(g_part);
    for (int c = c0; c < c1; c++) {
        float4 v = src[(size_t)c*E4 + e];
        sum.x += v.x; sum.y += v.y; sum.z += v.z; sum.w += v.w;
    }
    reinterpret_cast<float4*>(g_mid)[(size_t)blockIdx.y*E4 + e] = sum;
}
__global__ void reduce2_kernel() {
    int e = blockIdx.x * blockDim.x + threadIdx.x;
    if (e >= E4) return;
    float4 sum = make_float4(0.f, 0.f, 0.f, 0.f);
    const float4* src = reinterpret_cast<const float4*>(g_mid);
    for (int c = 0; c < 8; c++) {
        float4 v = src[(size_t)c*E4 + e];
        sum.x += v.x; sum.y += v.y; sum.z += v.z; sum.w += v.w;
    }
    reinterpret_cast<float4*>(g_p)[e] = sum;
}

// ---------------- min over valid 150x150 ----------------
__global__ void min_kernel() {
    __shared__ float sm[1024];
    int t = threadIdx.x;
    float m = 3.4e38f;
    for (int e = t; e < 22500; e += 1024) {
        int r = e / 150, c = e - r*150;
        m = fminf(m, g_p[r*CN + c]);
    }
    sm[t] = m;
    __syncthreads();
    for (int w2 = 512; w2 > 0; w2 >>= 1) {
        if (t < w2) sm[t] = fminf(sm[t], sm[t + w2]);
        __syncthreads();
    }
    if (t == 0) g_min[0] = sm[0];
}

// ---------------- loss epilogue (exact reference math, fp32) ----------------
__global__ void loss_kernel(float* __restrict__ out) {
    __shared__ float ssum[256];
    int t = threadIdx.x;
    float part = 0.0f;
    const float EPS = 1e-16f;
    if (t < TT) {
        int dy = t / TS, dx = t - dy*TS;
        const float m = g_min[0];
        float v[KCH*KCH];
        float tot = 0.0f;
        for (int n = 0; n < KCH; n++)
            for (int o = 0; o < KCH; o++) {
                float q = g_p[(dy*10 + n)*CN + (dx*10 + o)] - m + EPS;
                v[n*KCH + o] = q;
                tot += q;
            }
        float inv = 1.0f / tot;
        float pi[KCH], pj[KCH];
#pragma unroll
        for (int o = 0; o < KCH; o++) { pi[o] = 0.0f; pj[o] = 0.0f; }
        for (int n = 0; n < KCH; n++)
            for (int o = 0; o < KCH; o++) {
                float q = 0.5f * (v[n*KCH + o] + v[o*KCH + n]) * inv;
                pi[o] += q;
                pj[n] += q;
            }
        for (int n = 0; n < KCH; n++)
            for (int o = 0; o < KCH; o++) {
                float q = 0.5f * (v[n*KCH + o] + v[o*KCH + n]) * inv;
                part += -q * (logf(q + EPS) - logf(pi[o] + EPS) - logf(pj[n] + EPS));
            }
    }
    ssum[t] = part;
    __syncthreads();
    for (int w2 = 128; w2 > 0; w2 >>= 1) {
        if (t < w2) ssum[t] += ssum[t + w2];
        __syncthreads();
    }
    if (t == 0) out[0] = ssum[0] / (float)TT;
}

// ---------------- launch ----------------
extern "C" void kernel_launch(void* const* d_in, const int* in_sizes, int n_in,
                              void* d_out, int out_size) {
    const float* x = (const float*)d_in[0];   // x_out     (16,10,224,224) f32
    const float* y = (const float*)d_in[1];   // x_tf_out  (16,10,224,224) f32
    float* out = (float*)d_out;

    cudaFuncSetAttribute(gemm_kernel,
                         cudaFuncAttributeMaxDynamicSharedMemorySize, DSMEM);

    pack_x_f16<<<dim3((PS_X + 255)/256, KCH), 256>>>(x);
    pack_y_f16<<<dim3((PSY + 255)/256, KCH), 256>>>(y);
    gemm_kernel<<<GRIDG, 320, DSMEM>>>();
    reduce1_kernel<<<dim3((E4 + 255)/256, 8), 256>>>();
    reduce2_kernel<<<(E4 + 255)/256, 256>>>();
    min_kernel<<<1, 1024>>>();
    loss_kernel<<<1, 256>>>(out);
}

// round 10
// speedup vs baseline: 6.9080x; 1.0733x over previous
#include <cuda_runtime.h>
#include <cuda_fp16.h>
#include <cstdint>
#include <math.h>

#define BN    16
#define KCH   10
#define H     224
#define W     224
#define TS    15
#define TT    225

#define CROW  240                  // canvas row stride (elements)
#define S_IMG (238*CROW)           // 57120 per image
#define KU    (BN*S_IMG)           // 913920
#define PS_X  922368               // X canvas plane size
#define PSY   918848               // Y canvas plane size

#define TILEK 64
#define NTILE 97
#define CTAK  (NTILE*TILEK)        // 6208
#define GRIDG 148                  // 148*6208 = 918784 >= KU

#define SROW  144                  // smem row stride bytes (128B data + 16B pad)
#define MAT_BYTES (160*SROW)       // 23040
#define NSTAGE 3
#define DSMEM (NSTAGE*2*MAT_BYTES) // 138240

#define CN     160
#define PELEM2 (150*CN)            // 24000 per CTA
#define E4     (PELEM2/4)          // 6000

// ---------------- scratch ----------------
__device__ __align__(256) __half g_Xc[(size_t)KCH*PS_X];        // 18.4 MB
__device__ __align__(256) __half g_Yc[(size_t)4*KCH*PSY];       // 73.5 MB (4 parity canvases)
__device__ float g_part[(size_t)GRIDG*PELEM2];                  // 14.2 MB
__device__ float g_mid[(size_t)8*PELEM2];
__device__ float g_p[PELEM2];
__device__ float g_min[1];

// ---------------- PTX helpers (plain sm_80-era features only) ----------------
__device__ __forceinline__ uint32_t smem_u32(const void* p) {
    uint32_t a;
    asm("{ .reg .u64 t; cvta.to.shared.u64 t, %1; cvt.u32.u64 %0, t; }" : "=r"(a) : "l"(p));
    return a;
}
#define CP_COMMIT() asm volatile("cp.async.commit_group;" ::: "memory")
#define CP_WAIT1()  asm volatile("cp.async.wait_group 1;" ::: "memory")

__device__ __forceinline__ void ldsm4(uint32_t& r0, uint32_t& r1, uint32_t& r2, uint32_t& r3,
                                      uint32_t addr) {
    asm volatile("ldmatrix.sync.aligned.m8n8.x4.shared.b16 {%0,%1,%2,%3}, [%4];"
                 : "=r"(r0), "=r"(r1), "=r"(r2), "=r"(r3) : "r"(addr));
}
__device__ __forceinline__ void mma16816(float* d,
        uint32_t a0, uint32_t a1, uint32_t a2, uint32_t a3,
        uint32_t b0, uint32_t b1) {
    asm volatile("mma.sync.aligned.m16n8k16.row.col.f32.f16.f16.f32 "
                 "{%0,%1,%2,%3}, {%4,%5,%6,%7}, {%8,%9}, {%0,%1,%2,%3};"
                 : "+f"(d[0]), "+f"(d[1]), "+f"(d[2]), "+f"(d[3])
                 : "r"(a0), "r"(a1), "r"(a2), "r"(a3), "r"(b0), "r"(b1));
}

// ---------------- pack x_out -> zero-padded fp16 canvas ----------------
__global__ void pack_x_f16(const float* __restrict__ x) {
    int p = blockIdx.x * blockDim.x + threadIdx.x;
    int n = blockIdx.y;
    if (p >= PS_X) return;
    float v = 0.0f;
    if (p < KU) {
        int b  = p / S_IMG;
        int pp = p - b * S_IMG;
        int yy = pp / CROW, xx = pp - yy * CROW;
        if (yy >= 7 && yy < 231 && xx >= 7 && xx < 231)
            v = x[(((size_t)b*KCH + n)*H + (yy-7))*W + (xx-7)];
    }
    g_Xc[(size_t)n*PS_X + p] = __float2half(v);
}

// ---------------- pack x_tf_out -> 4 parity-shifted fp16 canvases ----------------
// Canvas s: C_s[q] = Y[q - 16 - s] (zero out of range); q in [0,16) stays module-zero.
__global__ void pack_y_f16(const float* __restrict__ y) {
    int p = blockIdx.x * blockDim.x + threadIdx.x;
    int o = blockIdx.y;
    if (p >= PSY) return;
    float v = 0.0f;
    if (p < KU) {
        int b  = p / S_IMG;
        int pp = p - b * S_IMG;
        int yy = pp / CROW, xx = pp - yy * CROW;
        if (yy < H && xx < W)
            v = y[(((size_t)b*KCH + o)*H + yy)*W + xx];
    }
    __half hv = __float2half(v);
#pragma unroll
    for (int s = 0; s < 4; s++) {
        int q = p + 16 + s;
        if (q < PSY) g_Yc[(size_t)(s*KCH + o)*PSY + q] = hv;
    }
}

// ---------------- trivial init: placed 3rd so gemm is the profiled 4th launch ----------------
__global__ void init_kernel() { g_min[0] = 0.0f; }

// ---------------- staging: gather A'/B' K=64 tiles into SMEM via cp.async ----------------
__device__ __forceinline__ void stage(int u0, uint32_t sA, uint32_t sB, int tid) {
    for (int i = tid; i < 1200; i += 320) {            // A: 150 rows x 8 x 16B
        int r = i >> 3, c = i & 7;
        int dy = r / 10, n = r - dy*10;
        const __half* src = g_Xc + (size_t)n*PS_X + (u0 + dy*CROW + c*8);
        asm volatile("cp.async.ca.shared.global [%0], [%1], 16;"
                     :: "r"(sA + r*SROW + c*16), "l"(src));
    }
    for (int i = tid; i < 2400; i += 320) {            // B: 150 rows x 16 x 8B
        int r = i >> 4, c = i & 15;
        int dx = r / 10, o = r - dx*10;
        int s = dx & 3;
        int q = u0 + c*4 - dx + s + 16;                // 8B aligned
        const __half* src = g_Yc + (size_t)(s*KCH + o)*PSY + q;
        asm volatile("cp.async.ca.shared.global [%0], [%1], 8;"
                     :: "r"(sB + r*SROW + c*8), "l"(src));
    }
}

// ---------------- per-tile warp MMA: m32 x n80, K=64 ----------------
__device__ __forceinline__ void compute_tile(uint32_t bufA, uint32_t bufB,
                                             int mBase, int nBase, int l,
                                             float acc[2][10][4]) {
    uint32_t aBase = bufA + (mBase + (l & 15))*SROW + ((l >> 4) & 1)*16;
    uint32_t bBase = bufB + (nBase + (l & 7) + ((l & 16) ? 8 : 0))*SROW + ((l & 8) ? 16 : 0);
#pragma unroll
    for (int kk = 0; kk < 4; kk++) {
        uint32_t a00, a01, a02, a03, a10, a11, a12, a13;
        ldsm4(a00, a01, a02, a03, aBase + kk*32);
        ldsm4(a10, a11, a12, a13, aBase + 16*SROW + kk*32);
#pragma unroll
        for (int t = 0; t < 5; t++) {
            uint32_t b0, b1, b2, b3;
            ldsm4(b0, b1, b2, b3, bBase + t*(16*SROW) + kk*32);
            mma16816(acc[0][2*t],     a00, a01, a02, a03, b0, b1);
            mma16816(acc[0][2*t + 1], a00, a01, a02, a03, b2, b3);
            mma16816(acc[1][2*t],     a10, a11, a12, a13, b0, b1);
            mma16816(acc[1][2*t + 1], a10, a11, a12, a13, b2, b3);
        }
    }
}

// ---------------- GEMM: C[150,150] += A'·B'^T over this CTA's K chunk ----------------
__global__ __launch_bounds__(320, 1) void gemm_kernel() {
    extern __shared__ char smem[];
    uint32_t sb = smem_u32(smem);
    int tid = threadIdx.x;
    int w = tid >> 5, l = tid & 31;
    int mBase = (w % 5) * 32;
    int nBase = (w / 5) * 80;

    // zero pad rows 150-159 of all 6 matrices (never touched by staging)
    for (int i = tid; i < NSTAGE*2*360; i += 320) {
        int mtx = i / 360, off = i - mtx*360;
        *reinterpret_cast<uint32_t*>(smem + mtx*MAT_BYTES + 150*SROW + off*4) = 0;
    }

    int u0 = blockIdx.x * CTAK;

    // prologue: stages 0 and 1
    stage(u0,         sb,                 sb + MAT_BYTES,                 tid);
    CP_COMMIT();
    stage(u0 + TILEK, sb + 2*MAT_BYTES,   sb + 3*MAT_BYTES,               tid);
    CP_COMMIT();

    float acc[2][10][4];
#pragma unroll
    for (int s = 0; s < 2; s++)
#pragma unroll
        for (int j = 0; j < 10; j++)
#pragma unroll
            for (int c = 0; c < 4; c++) acc[s][j][c] = 0.0f;

    for (int i = 0; i < NTILE; i++) {
        CP_WAIT1();                // group i complete (all but newest outstanding)
        __syncthreads();           // tile i visible; everyone done with tile i-1
        if (i + 2 < NTILE) {
            int m = (i + 2) % NSTAGE;
            stage(u0 + (i + 2)*TILEK, sb + m*(2*MAT_BYTES),
                  sb + m*(2*MAT_BYTES) + MAT_BYTES, tid);
        }
        CP_COMMIT();               // uniform group count (possibly empty)
        int cm = i % NSTAGE;
        compute_tile(sb + cm*(2*MAT_BYTES), sb + cm*(2*MAT_BYTES) + MAT_BYTES,
                     mBase, nBase, l, acc);
    }

    // epilogue: fragment rows mBase+16s+{l>>2, +8}; cols nBase + j*8 + 2*(l&3)
    float* dst = g_part + (size_t)blockIdx.x * PELEM2;
#pragma unroll
    for (int s = 0; s < 2; s++) {
        int r0 = mBase + 16*s + (l >> 2);
#pragma unroll
        for (int j = 0; j < 10; j++) {
            int n = nBase + j*8 + 2*(l & 3);
            if (r0 < 150) {
                dst[r0*CN + n]     = acc[s][j][0];
                dst[r0*CN + n + 1] = acc[s][j][1];
            }
            if (r0 + 8 < 150) {
                dst[(r0 + 8)*CN + n]     = acc[s][j][2];
                dst[(r0 + 8)*CN + n + 1] = acc[s][j][3];
            }
        }
    }
}

// ---------------- reduce partials (2-stage) ----------------
__global__ void reduce1_kernel() {
    int e = blockIdx.x * blockDim.x + threadIdx.x;   // float4 index
    if (e >= E4) return;
    int c0 = blockIdx.y * 19;
    int c1 = min(c0 + 19, GRIDG);
    float4 sum = make_float4(0.f, 0.f, 0.f, 0.f);
    const float4* src = reinterpret_cast<const float4*>(g_part);
    for (int c = c0; c < c1; c++) {
        float4 v = src[(size_t)c*E4 + e];
        sum.x += v.x; sum.y += v.y; sum.z += v.z; sum.w += v.w;
    }
    reinterpret_cast<float4*>(g_mid)[(size_t)blockIdx.y*E4 + e] = sum;
}
__global__ void reduce2_kernel() {
    int e = blockIdx.x * blockDim.x + threadIdx.x;
    if (e >= E4) return;
    float4 sum = make_float4(0.f, 0.f, 0.f, 0.f);
    const float4* src = reinterpret_cast<const float4*>(g_mid);
    for (int c = 0; c < 8; c++) {
        float4 v = src[(size_t)c*E4 + e];
        sum.x += v.x; sum.y += v.y; sum.z += v.z; sum.w += v.w;
    }
    reinterpret_cast<float4*>(g_p)[e] = sum;
}

// ---------------- min over valid 150x150 ----------------
__global__ void min_kernel() {
    __shared__ float sm[1024];
    int t = threadIdx.x;
    float m = 3.4e38f;
    for (int e = t; e < 22500; e += 1024) {
        int r = e / 150, c = e - r*150;
        m = fminf(m, g_p[r*CN + c]);
    }
    sm[t] = m;
    __syncthreads();
    for (int w2 = 512; w2 > 0; w2 >>= 1) {
        if (t < w2) sm[t] = fminf(sm[t], sm[t + w2]);
        __syncthreads();
    }
    if (t == 0) g_min[0] = sm[0];
}

// ---------------- loss epilogue (exact reference math, fp32) ----------------
__global__ void loss_kernel(float* __restrict__ out) {
    __shared__ float ssum[256];
    int t = threadIdx.x;
    float part = 0.0f;
    const float EPS = 1e-16f;
    if (t < TT) {
        int dy = t / TS, dx = t - dy*TS;
        const float m = g_min[0];
        float v[KCH*KCH];
        float tot = 0.0f;
        for (int n = 0; n < KCH; n++)
            for (int o = 0; o < KCH; o++) {
                float q = g_p[(dy*10 + n)*CN + (dx*10 + o)] - m + EPS;
                v[n*KCH + o] = q;
                tot += q;
            }
        float inv = 1.0f / tot;
        float pi[KCH], pj[KCH];
#pragma unroll
        for (int o = 0; o < KCH; o++) { pi[o] = 0.0f; pj[o] = 0.0f; }
        for (int n = 0; n < KCH; n++)
            for (int o = 0; o < KCH; o++) {
                float q = 0.5f * (v[n*KCH + o] + v[o*KCH + n]) * inv;
                pi[o] += q;
                pj[n] += q;
            }
        for (int n = 0; n < KCH; n++)
            for (int o = 0; o < KCH; o++) {
                float q = 0.5f * (v[n*KCH + o] + v[o*KCH + n]) * inv;
                part += -q * (logf(q + EPS) - logf(pi[o] + EPS) - logf(pj[n] + EPS));
            }
    }
    ssum[t] = part;
    __syncthreads();
    for (int w2 = 128; w2 > 0; w2 >>= 1) {
        if (t < w2) ssum[t] += ssum[t + w2];
        __syncthreads();
    }
    if (t == 0) out[0] = ssum[0] / (float)TT;
}

// ---------------- launch ----------------
extern "C" void kernel_launch(void* const* d_in, const int* in_sizes, int n_in,
                              void* d_out, int out_size) {
    const float* x = (const float*)d_in[0];   // x_out     (16,10,224,224) f32
    const float* y = (const float*)d_in[1];   // x_tf_out  (16,10,224,224) f32
    float* out = (float*)d_out;

    cudaFuncSetAttribute(gemm_kernel,
                         cudaFuncAttributeMaxDynamicSharedMemorySize, DSMEM);

    pack_x_f16<<<dim3((PS_X + 255)/256, KCH), 256>>>(x);
    pack_y_f16<<<dim3((PSY + 255)/256, KCH), 256>>>(y);
    init_kernel<<<1, 1>>>();                       // launch #3 -> gemm profiled as #4
    gemm_kernel<<<GRIDG, 320, DSMEM>>>();
    reduce1_kernel<<<dim3((E4 + 255)/256, 8), 256>>>();
    reduce2_kernel<<<(E4 + 255)/256, 256>>>();
    min_kernel<<<1, 1024>>>();
    loss_kernel<<<1, 256>>>(out);
}

// round 14
// speedup vs baseline: 7.6992x; 1.1145x over previous
#include <cuda_runtime.h>
#include <cuda_fp16.h>
#include <cstdint>
#include <math.h>

#define BN    16
#define KCH   10
#define H     224
#define W     224
#define TS    15
#define TT    225

#define CROW  240                  // canvas row stride (elements)
#define S_IMG (238*CROW)           // 57120 per image
#define KU    (BN*S_IMG)           // 913920
#define PS_X  922368               // X canvas plane size
#define PSY   918848               // Y canvas plane size

#define TILEK 64
#define NTILE 97
#define CTAK  (NTILE*TILEK)        // 6208
#define GRIDG 148                  // 148*6208 = 918784 >= KU

#define NT    640                  // 20 warps: 5 per SMSP, balanced

#define SROW  144                  // smem row stride bytes (128B data + 16B pad)
#define MAT_BYTES (160*SROW)       // 23040
#define NSTAGE 3
#define DSMEM (NSTAGE*2*MAT_BYTES) // 138240

#define CN     160
#define PELEM2 (150*CN)            // 24000 per CTA
#define E4     (PELEM2/4)          // 6000

// ---------------- scratch ----------------
__device__ __align__(256) __half g_Xc[(size_t)KCH*PS_X];        // 18.4 MB
__device__ __align__(256) __half g_Yc[(size_t)4*KCH*PSY];       // 73.5 MB (4 parity canvases)
__device__ float g_part[(size_t)GRIDG*PELEM2];                  // 14.2 MB
__device__ float g_mid[(size_t)8*PELEM2];
__device__ float g_p[PELEM2];
__device__ float g_min[1];

// ---------------- PTX helpers (plain sm_80-era features only) ----------------
__device__ __forceinline__ uint32_t smem_u32(const void* p) {
    uint32_t a;
    asm("{ .reg .u64 t; cvta.to.shared.u64 t, %1; cvt.u32.u64 %0, t; }" : "=r"(a) : "l"(p));
    return a;
}
#define CP_COMMIT() asm volatile("cp.async.commit_group;" ::: "memory")
#define CP_WAIT1()  asm volatile("cp.async.wait_group 1;" ::: "memory")

__device__ __forceinline__ void ldsm4(uint32_t& r0, uint32_t& r1, uint32_t& r2, uint32_t& r3,
                                      uint32_t addr) {
    asm volatile("ldmatrix.sync.aligned.m8n8.x4.shared.b16 {%0,%1,%2,%3}, [%4];"
                 : "=r"(r0), "=r"(r1), "=r"(r2), "=r"(r3) : "r"(addr));
}
__device__ __forceinline__ void ldsm2(uint32_t& r0, uint32_t& r1, uint32_t addr) {
    asm volatile("ldmatrix.sync.aligned.m8n8.x2.shared.b16 {%0,%1}, [%2];"
                 : "=r"(r0), "=r"(r1) : "r"(addr));
}
__device__ __forceinline__ void mma16816(float* d,
        uint32_t a0, uint32_t a1, uint32_t a2, uint32_t a3,
        uint32_t b0, uint32_t b1) {
    asm volatile("mma.sync.aligned.m16n8k16.row.col.f32.f16.f16.f32 "
                 "{%0,%1,%2,%3}, {%4,%5,%6,%7}, {%8,%9}, {%0,%1,%2,%3};"
                 : "+f"(d[0]), "+f"(d[1]), "+f"(d[2]), "+f"(d[3])
                 : "r"(a0), "r"(a1), "r"(a2), "r"(a3), "r"(b0), "r"(b1));
}

// ---------------- pack x_out -> zero-padded fp16 canvas ----------------
__global__ void pack_x_f16(const float* __restrict__ x) {
    int p = blockIdx.x * blockDim.x + threadIdx.x;
    int n = blockIdx.y;
    if (p >= PS_X) return;
    float v = 0.0f;
    if (p < KU) {
        int b  = p / S_IMG;
        int pp = p - b * S_IMG;
        int yy = pp / CROW, xx = pp - yy * CROW;
        if (yy >= 7 && yy < 231 && xx >= 7 && xx < 231)
            v = x[(((size_t)b*KCH + n)*H + (yy-7))*W + (xx-7)];
    }
    g_Xc[(size_t)n*PS_X + p] = __float2half(v);
}

// ---------------- pack x_tf_out -> 4 parity-shifted fp16 canvases ----------------
// Canvas s: C_s[q] = Y[q - 16 - s] (zero out of range); q in [0,16) stays module-zero.
__global__ void pack_y_f16(const float* __restrict__ y) {
    int p = blockIdx.x * blockDim.x + threadIdx.x;
    int o = blockIdx.y;
    if (p >= PSY) return;
    float v = 0.0f;
    if (p < KU) {
        int b  = p / S_IMG;
        int pp = p - b * S_IMG;
        int yy = pp / CROW, xx = pp - yy * CROW;
        if (yy < H && xx < W)
            v = y[(((size_t)b*KCH + o)*H + yy)*W + xx];
    }
    __half hv = __float2half(v);
#pragma unroll
    for (int s = 0; s < 4; s++) {
        int q = p + 16 + s;
        if (q < PSY) g_Yc[(size_t)(s*KCH + o)*PSY + q] = hv;
    }
}

// ---------------- trivial init: placed 3rd so gemm is the profiled 4th launch ----------------
__global__ void init_kernel() { g_min[0] = 0.0f; }

// ---------------- staging: gather A'/B' K=64 tiles into SMEM via cp.async ----------------
__device__ __forceinline__ void stage(int u0, uint32_t sA, uint32_t sB, int tid) {
#pragma unroll 2
    for (int i = tid; i < 1200; i += NT) {             // A: 150 rows x 8 x 16B
        int r = i >> 3, c = i & 7;
        int dy = r / 10, n = r - dy*10;
        const __half* src = g_Xc + (size_t)n*PS_X + (u0 + dy*CROW + c*8);
        asm volatile("cp.async.ca.shared.global [%0], [%1], 16;"
                     :: "r"(sA + r*SROW + c*16), "l"(src));
    }
#pragma unroll 4
    for (int i = tid; i < 2400; i += NT) {             // B: 150 rows x 16 x 8B
        int r = i >> 4, c = i & 15;
        int dx = r / 10, o = r - dx*10;
        int s = dx & 3;
        int q = u0 + c*4 - dx + s + 16;                // 8B aligned
        const __half* src = g_Yc + (size_t)(s*KCH + o)*PSY + q;
        asm volatile("cp.async.ca.shared.global [%0], [%1], 8;"
                     :: "r"(sB + r*SROW + c*8), "l"(src));
    }
}

// ---------------- per-tile warp MMA: m32 x n40, K=64 ----------------
__device__ __forceinline__ void compute_tile(uint32_t bufA, uint32_t bufB,
                                             int mBase, int nBase, int l,
                                             float acc[2][5][4]) {
    uint32_t aBase = bufA + (mBase + (l & 15))*SROW + ((l >> 4) & 1)*16;
    uint32_t bBase4 = bufB + (nBase + (l & 7) + ((l & 16) ? 8 : 0))*SROW + ((l & 8) ? 16 : 0);
    uint32_t bBase2 = bufB + (nBase + 32 + (l & 7))*SROW + ((l & 8) ? 16 : 0);
#pragma unroll
    for (int kk = 0; kk < 4; kk++) {
        uint32_t a00, a01, a02, a03, a10, a11, a12, a13;
        ldsm4(a00, a01, a02, a03, aBase + kk*32);
        ldsm4(a10, a11, a12, a13, aBase + 16*SROW + kk*32);
        uint32_t b0, b1, b2, b3, b4, b5, b6, b7, b8, b9;
        ldsm4(b0, b1, b2, b3, bBase4 + kk*32);                // n8 tiles 0,1
        ldsm4(b4, b5, b6, b7, bBase4 + 16*SROW + kk*32);      // n8 tiles 2,3
        ldsm2(b8, b9, bBase2 + kk*32);                        // n8 tile 4
        mma16816(acc[0][0], a00, a01, a02, a03, b0, b1);
        mma16816(acc[0][1], a00, a01, a02, a03, b2, b3);
        mma16816(acc[0][2], a00, a01, a02, a03, b4, b5);
        mma16816(acc[0][3], a00, a01, a02, a03, b6, b7);
        mma16816(acc[0][4], a00, a01, a02, a03, b8, b9);
        mma16816(acc[1][0], a10, a11, a12, a13, b0, b1);
        mma16816(acc[1][1], a10, a11, a12, a13, b2, b3);
        mma16816(acc[1][2], a10, a11, a12, a13, b4, b5);
        mma16816(acc[1][3], a10, a11, a12, a13, b6, b7);
        mma16816(acc[1][4], a10, a11, a12, a13, b8, b9);
    }
}

// ---------------- GEMM: C[150,150] += A'·B'^T over this CTA's K chunk ----------------
__global__ __launch_bounds__(NT, 1) void gemm_kernel() {
    extern __shared__ char smem[];
    uint32_t sb = smem_u32(smem);
    int tid = threadIdx.x;
    int w = tid >> 5, l = tid & 31;
    int mBase = (w % 5) * 32;      // 5 m-strips of 32
    int nBase = (w / 5) * 40;      // 4 n-quarters of 40

    // zero pad rows 150-159 of all 6 matrices (never touched by staging)
    for (int i = tid; i < NSTAGE*2*360; i += NT) {
        int mtx = i / 360, off = i - mtx*360;
        *reinterpret_cast<uint32_t*>(smem + mtx*MAT_BYTES + 150*SROW + off*4) = 0;
    }

    int u0 = blockIdx.x * CTAK;

    // prologue: stages 0 and 1
    stage(u0,         sb,                 sb + MAT_BYTES,   tid);
    CP_COMMIT();
    stage(u0 + TILEK, sb + 2*MAT_BYTES,   sb + 3*MAT_BYTES, tid);
    CP_COMMIT();

    float acc[2][5][4];
#pragma unroll
    for (int s = 0; s < 2; s++)
#pragma unroll
        for (int j = 0; j < 5; j++)
#pragma unroll
            for (int c = 0; c < 4; c++) acc[s][j][c] = 0.0f;

    for (int i = 0; i < NTILE; i++) {
        CP_WAIT1();                // group i complete (all but newest outstanding)
        __syncthreads();           // tile i visible; everyone done with tile i-1
        if (i + 2 < NTILE) {
            int m = (i + 2) % NSTAGE;
            stage(u0 + (i + 2)*TILEK, sb + m*(2*MAT_BYTES),
                  sb + m*(2*MAT_BYTES) + MAT_BYTES, tid);
        }
        CP_COMMIT();               // uniform group count (possibly empty)
        int cm = i % NSTAGE;
        compute_tile(sb + cm*(2*MAT_BYTES), sb + cm*(2*MAT_BYTES) + MAT_BYTES,
                     mBase, nBase, l, acc);
    }

    // epilogue: fragment rows mBase+16s+{l>>2, +8}; cols nBase + j*8 + 2*(l&3)
    float* dst = g_part + (size_t)blockIdx.x * PELEM2;
#pragma unroll
    for (int s = 0; s < 2; s++) {
        int r0 = mBase + 16*s + (l >> 2);
#pragma unroll
        for (int j = 0; j < 5; j++) {
            int n = nBase + j*8 + 2*(l & 3);
            if (r0 < 150) {
                dst[r0*CN + n]     = acc[s][j][0];
                dst[r0*CN + n + 1] = acc[s][j][1];
            }
            if (r0 + 8 < 150) {
                dst[(r0 + 8)*CN + n]     = acc[s][j][2];
                dst[(r0 + 8)*CN + n + 1] = acc[s][j][3];
            }
        }
    }
}

// ---------------- reduce partials (2-stage) ----------------
__global__ void reduce1_kernel() {
    int e = blockIdx.x * blockDim.x + threadIdx.x;   // float4 index
    if (e >= E4) return;
    int c0 = blockIdx.y * 19;
    int c1 = min(c0 + 19, GRIDG);
    float4 sum = make_float4(0.f, 0.f, 0.f, 0.f);
    const float4* src = reinterpret_cast<const float4*>(g_part);
    for (int c = c0; c < c1; c++) {
        float4 v = src[(size_t)c*E4 + e];
        sum.x += v.x; sum.y += v.y; sum.z += v.z; sum.w += v.w;
    }
    reinterpret_cast<float4*>(g_mid)[(size_t)blockIdx.y*E4 + e] = sum;
}
__global__ void reduce2_kernel() {
    int e = blockIdx.x * blockDim.x + threadIdx.x;
    if (e >= E4) return;
    float4 sum = make_float4(0.f, 0.f, 0.f, 0.f);
    const float4* src = reinterpret_cast<const float4*>(g_mid);
    for (int c = 0; c < 8; c++) {
        float4 v = src[(size_t)c*E4 + e];
        sum.x += v.x; sum.y += v.y; sum.z += v.z; sum.w += v.w;
    }
    reinterpret_cast<float4*>(g_p)[e] = sum;
}

// ---------------- min over valid 150x150 ----------------
__global__ void min_kernel() {
    __shared__ float sm[1024];
    int t = threadIdx.x;
    float m = 3.4e38f;
    for (int e = t; e < 22500; e += 1024) {
        int r = e / 150, c = e - r*150;
        m = fminf(m, g_p[r*CN + c]);
    }
    sm[t] = m;
    __syncthreads();
    for (int w2 = 512; w2 > 0; w2 >>= 1) {
        if (t < w2) sm[t] = fminf(sm[t], sm[t + w2]);
        __syncthreads();
    }
    if (t == 0) g_min[0] = sm[0];
}

// ---------------- loss epilogue (exact reference math, fp32) ----------------
__global__ void loss_kernel(float* __restrict__ out) {
    __shared__ float ssum[256];
    int t = threadIdx.x;
    float part = 0.0f;
    const float EPS = 1e-16f;
    if (t < TT) {
        int dy = t / TS, dx = t - dy*TS;
        const float m = g_min[0];
        float v[KCH*KCH];
        float tot = 0.0f;
        for (int n = 0; n < KCH; n++)
            for (int o = 0; o < KCH; o++) {
                float q = g_p[(dy*10 + n)*CN + (dx*10 + o)] - m + EPS;
                v[n*KCH + o] = q;
                tot += q;
            }
        float inv = 1.0f / tot;
        float pi[KCH], pj[KCH];
#pragma unroll
        for (int o = 0; o < KCH; o++) { pi[o] = 0.0f; pj[o] = 0.0f; }
        for (int n = 0; n < KCH; n++)
            for (int o = 0; o < KCH; o++) {
                float q = 0.5f * (v[n*KCH + o] + v[o*KCH + n]) * inv;
                pi[o] += q;
                pj[n] += q;
            }
        for (int n = 0; n < KCH; n++)
            for (int o = 0; o < KCH; o++) {
                float q = 0.5f * (v[n*KCH + o] + v[o*KCH + n]) * inv;
                part += -q * (logf(q + EPS) - logf(pi[o] + EPS) - logf(pj[n] + EPS));
            }
    }
    ssum[t] = part;
    __syncthreads();
    for (int w2 = 128; w2 > 0; w2 >>= 1) {
        if (t < w2) ssum[t] += ssum[t + w2];
        __syncthreads();
    }
    if (t == 0) out[0] = ssum[0] / (float)TT;
}

// ---------------- launch ----------------
extern "C" void kernel_launch(void* const* d_in, const int* in_sizes, int n_in,
                              void* d_out, int out_size) {
    const float* x = (const float*)d_in[0];   // x_out     (16,10,224,224) f32
    const float* y = (const float*)d_in[1];   // x_tf_out  (16,10,224,224) f32
    float* out = (float*)d_out;

    cudaFuncSetAttribute(gemm_kernel,
                         cudaFuncAttributeMaxDynamicSharedMemorySize, DSMEM);

    pack_x_f16<<<dim3((PS_X + 255)/256, KCH), 256>>>(x);
    pack_y_f16<<<dim3((PSY + 255)/256, KCH), 256>>>(y);
    init_kernel<<<1, 1>>>();                       // launch #3 -> gemm profiled as #4
    gemm_kernel<<<GRIDG, NT, DSMEM>>>();
    reduce1_kernel<<<dim3((E4 + 255)/256, 8), 256>>>();
    reduce2_kernel<<<(E4 + 255)/256, 256>>>();
    min_kernel<<<1, 1024>>>();
    loss_kernel<<<1, 256>>>(out);
}